// round 1
// baseline (speedup 1.0000x reference)
#include <cuda_runtime.h>

#define NA   8
#define BSZ  4
#define THW  1024
#define DD   512
#define DA   64
#define NROWS (BSZ*THW)   // 4096

// Scratch (device globals; allocation is forbidden)
__device__ float g_xn[NROWS * DD];            // 8 MB   normalized x
__device__ float g_q [NA * NROWS * DA];       // 8 MB   q (pre-scaled by 1/8)
__device__ float g_k [NA * NROWS * DA];       // 8 MB
__device__ float g_v [NA * NROWS * DA];       // 8 MB
__device__ float g_s [33554432];              // 128 MB scores/probs [NA][BSZ][THW][THW]
__device__ float g_ao[NROWS * DD];            // 8 MB   concat attention output

// ---------------------------------------------------------------- LayerNorm
__global__ void ln_kernel(const float* __restrict__ x,
                          const float* __restrict__ gamma,
                          const float* __restrict__ beta) {
    int row = blockIdx.x;
    int t   = threadIdx.x;              // 128 threads
    const float* xr = x + (size_t)row * DD;
    float v[4];
    float s = 0.f;
#pragma unroll
    for (int i = 0; i < 4; i++) { v[i] = xr[i * 128 + t]; s += v[i]; }

    __shared__ float rbuf[4];
    __shared__ float stat;
#pragma unroll
    for (int o = 16; o > 0; o >>= 1) s += __shfl_xor_sync(0xffffffffu, s, o);
    if ((t & 31) == 0) rbuf[t >> 5] = s;
    __syncthreads();
    if (t == 0) stat = rbuf[0] + rbuf[1] + rbuf[2] + rbuf[3];
    __syncthreads();
    float mean = stat * (1.f / DD);

    float ss = 0.f;
#pragma unroll
    for (int i = 0; i < 4; i++) { float d = v[i] - mean; ss += d * d; }
    __syncthreads();   // protect rbuf/stat reuse
#pragma unroll
    for (int o = 16; o > 0; o >>= 1) ss += __shfl_xor_sync(0xffffffffu, ss, o);
    if ((t & 31) == 0) rbuf[t >> 5] = ss;
    __syncthreads();
    if (t == 0) stat = rbuf[0] + rbuf[1] + rbuf[2] + rbuf[3];
    __syncthreads();
    float rstd = rsqrtf(stat * (1.f / DD) + 1e-5f);

    float* xo = g_xn + (size_t)row * DD;
#pragma unroll
    for (int i = 0; i < 4; i++) {
        int c = i * 128 + t;
        xo[c] = (v[i] - mean) * rstd * gamma[c] + beta[c];
    }
}

// ---------------------------------------------------------------- QKV GEMM
// out[h][n][e] = sum_d xn[n][d] * w[h][d][e];   q additionally * 1/8
__global__ __launch_bounds__(256) void qkv_kernel(const float* __restrict__ wq,
                                                  const float* __restrict__ wk,
                                                  const float* __restrict__ wv) {
    int h     = blockIdx.y;
    int which = blockIdx.z;
    const float* w = (which == 0) ? wq : ((which == 1) ? wk : wv);
    float* out     = (which == 0) ? g_q : ((which == 1) ? g_k : g_v);
    w   += (size_t)h * DD * DA;
    out += (size_t)h * NROWS * DA;
    int row0 = blockIdx.x * 64;

    __shared__ float As[64][65];   // [k][row]  (transposed)
    __shared__ float Bs[64][64];   // [k][col]
    int tid = threadIdx.x, tx = tid & 15, ty = tid >> 4;
    float acc[4][4] = {};

    for (int k0 = 0; k0 < DD; k0 += 64) {
#pragma unroll
        for (int l = 0; l < 4; l++) {
            int flat = l * 256 + tid;
            int r = flat >> 4, c4 = flat & 15;
            float4 a = *(const float4*)&g_xn[(size_t)(row0 + r) * DD + k0 + c4 * 4];
            As[c4*4+0][r] = a.x; As[c4*4+1][r] = a.y;
            As[c4*4+2][r] = a.z; As[c4*4+3][r] = a.w;
            *(float4*)&Bs[r][c4 * 4] = *(const float4*)&w[(size_t)(k0 + r) * DA + c4 * 4];
        }
        __syncthreads();
#pragma unroll
        for (int kk = 0; kk < 64; kk++) {
            float a[4], b[4];
#pragma unroll
            for (int i = 0; i < 4; i++) a[i] = As[kk][ty * 4 + i];
#pragma unroll
            for (int j = 0; j < 4; j++) b[j] = Bs[kk][tx * 4 + j];
#pragma unroll
            for (int i = 0; i < 4; i++)
#pragma unroll
                for (int j = 0; j < 4; j++) acc[i][j] = fmaf(a[i], b[j], acc[i][j]);
        }
        __syncthreads();
    }
    float scale = (which == 0) ? 0.125f : 1.0f;   // 1/sqrt(DA)
#pragma unroll
    for (int i = 0; i < 4; i++) {
        float4 r = make_float4(acc[i][0]*scale, acc[i][1]*scale,
                               acc[i][2]*scale, acc[i][3]*scale);
        *(float4*)&out[(size_t)(row0 + ty*4 + i) * DA + tx * 4] = r;
    }
}

// ------------------------------------------------- scores = qk^T + bias, mask
__global__ __launch_bounds__(256) void scores_kernel(const float* __restrict__ Bb,
                                                     const int* __restrict__ M) {
    int hb = blockIdx.z;
    size_t qk_off = ((size_t)(hb >> 2) * NROWS + (size_t)(hb & 3) * THW) * DA;
    const float* q = g_q + qk_off;
    const float* k = g_k + qk_off;
    float* S        = g_s + (size_t)hb * THW * THW;
    const float* Bp = Bb  + (size_t)hb * THW * THW;
    int qr0 = blockIdx.y * 64, kc0 = blockIdx.x * 64;

    __shared__ float Qs[64][65];   // [e][qrow]
    __shared__ float Ks[64][65];   // [e][krow]
    int tid = threadIdx.x, tx = tid & 15, ty = tid >> 4;
#pragma unroll
    for (int l = 0; l < 4; l++) {
        int flat = l * 256 + tid;
        int r = flat >> 4, c4 = flat & 15;
        float4 a = *(const float4*)&q[(size_t)(qr0 + r) * DA + c4 * 4];
        Qs[c4*4+0][r] = a.x; Qs[c4*4+1][r] = a.y;
        Qs[c4*4+2][r] = a.z; Qs[c4*4+3][r] = a.w;
        float4 b = *(const float4*)&k[(size_t)(kc0 + r) * DA + c4 * 4];
        Ks[c4*4+0][r] = b.x; Ks[c4*4+1][r] = b.y;
        Ks[c4*4+2][r] = b.z; Ks[c4*4+3][r] = b.w;
    }
    __syncthreads();
    float acc[4][4] = {};
#pragma unroll
    for (int kk = 0; kk < 64; kk++) {
        float a[4], b[4];
#pragma unroll
        for (int i = 0; i < 4; i++) a[i] = Qs[kk][ty * 4 + i];
#pragma unroll
        for (int j = 0; j < 4; j++) b[j] = Ks[kk][tx * 4 + j];
#pragma unroll
        for (int i = 0; i < 4; i++)
#pragma unroll
            for (int j = 0; j < 4; j++) acc[i][j] = fmaf(a[i], b[j], acc[i][j]);
    }
#pragma unroll
    for (int i = 0; i < 4; i++) {
        int qq = qr0 + ty * 4 + i;
        size_t off = (size_t)qq * THW + kc0 + tx * 4;
        float4 bb = *(const float4*)&Bp[off];
        int4   mm = *(const int4*)&M[off];
        float4 r;
        r.x = mm.x ? -10000.f : acc[i][0] + bb.x;
        r.y = mm.y ? -10000.f : acc[i][1] + bb.y;
        r.z = mm.z ? -10000.f : acc[i][2] + bb.z;
        r.w = mm.w ? -10000.f : acc[i][3] + bb.w;
        *(float4*)&S[off] = r;
    }
}

// ---------------------------------------------------------------- softmax
__global__ void softmax_kernel() {
    float* S = g_s + (size_t)blockIdx.x * THW;
    int t = threadIdx.x;            // 256 threads, 4 elems each
    float4 v = *(float4*)&S[t * 4];
    float m = fmaxf(fmaxf(v.x, v.y), fmaxf(v.z, v.w));
    __shared__ float rbuf[8];
    __shared__ float stat;
#pragma unroll
    for (int o = 16; o > 0; o >>= 1) m = fmaxf(m, __shfl_xor_sync(0xffffffffu, m, o));
    if ((t & 31) == 0) rbuf[t >> 5] = m;
    __syncthreads();
    if (t == 0) {
        float mm = rbuf[0];
#pragma unroll
        for (int i = 1; i < 8; i++) mm = fmaxf(mm, rbuf[i]);
        stat = mm;
    }
    __syncthreads();
    m = stat;
    v.x = __expf(v.x - m); v.y = __expf(v.y - m);
    v.z = __expf(v.z - m); v.w = __expf(v.w - m);
    float s = v.x + v.y + v.z + v.w;
    __syncthreads();
#pragma unroll
    for (int o = 16; o > 0; o >>= 1) s += __shfl_xor_sync(0xffffffffu, s, o);
    if ((t & 31) == 0) rbuf[t >> 5] = s;
    __syncthreads();
    if (t == 0) {
        float ss = 0.f;
#pragma unroll
        for (int i = 0; i < 8; i++) ss += rbuf[i];
        stat = ss;
    }
    __syncthreads();
    float inv = 1.f / stat;
    v.x *= inv; v.y *= inv; v.z *= inv; v.w *= inv;
    *(float4*)&S[t * 4] = v;
}

// ---------------------------------------------------------------- PV GEMM
__global__ __launch_bounds__(256) void pv_kernel() {
    int hb = blockIdx.y;
    int h = hb >> 2, b = hb & 3;
    const float* P = g_s + (size_t)hb * THW * THW;
    const float* V = g_v + ((size_t)h * NROWS + (size_t)b * THW) * DA;
    int qr0 = blockIdx.x * 64;

    __shared__ float Ps[64][65];   // [t][q]
    __shared__ float Vs[64][64];   // [t][e]
    int tid = threadIdx.x, tx = tid & 15, ty = tid >> 4;
    float acc[4][4] = {};

    for (int t0 = 0; t0 < THW; t0 += 64) {
#pragma unroll
        for (int l = 0; l < 4; l++) {
            int flat = l * 256 + tid;
            int r = flat >> 4, c4 = flat & 15;
            float4 a = *(const float4*)&P[(size_t)(qr0 + r) * THW + t0 + c4 * 4];
            Ps[c4*4+0][r] = a.x; Ps[c4*4+1][r] = a.y;
            Ps[c4*4+2][r] = a.z; Ps[c4*4+3][r] = a.w;
            *(float4*)&Vs[r][c4 * 4] = *(const float4*)&V[(size_t)(t0 + r) * DA + c4 * 4];
        }
        __syncthreads();
#pragma unroll
        for (int kk = 0; kk < 64; kk++) {
            float a[4], bb[4];
#pragma unroll
            for (int i = 0; i < 4; i++) a[i] = Ps[kk][ty * 4 + i];
#pragma unroll
            for (int j = 0; j < 4; j++) bb[j] = Vs[kk][tx * 4 + j];
#pragma unroll
            for (int i = 0; i < 4; i++)
#pragma unroll
                for (int j = 0; j < 4; j++) acc[i][j] = fmaf(a[i], bb[j], acc[i][j]);
        }
        __syncthreads();
    }
#pragma unroll
    for (int i = 0; i < 4; i++) {
        int row = b * THW + qr0 + ty * 4 + i;
        float4 r = make_float4(acc[i][0], acc[i][1], acc[i][2], acc[i][3]);
        *(float4*)&g_ao[(size_t)row * DD + h * DA + tx * 4] = r;
    }
}

// ------------------------------------------------- proj + residual
// y[n][o] = sum_i ao[n][i] * wp[o][i] + x[n][o]
__global__ __launch_bounds__(256) void proj_kernel(const float* __restrict__ x,
                                                   const float* __restrict__ wp,
                                                   float* __restrict__ out) {
    int r0 = blockIdx.y * 64, c0 = blockIdx.x * 64;
    __shared__ float As[64][65];   // [i][n]
    __shared__ float Ws[64][65];   // [i][o]
    int tid = threadIdx.x, tx = tid & 15, ty = tid >> 4;
    float acc[4][4] = {};

    for (int k0 = 0; k0 < DD; k0 += 64) {
#pragma unroll
        for (int l = 0; l < 4; l++) {
            int flat = l * 256 + tid;
            int r = flat >> 4, c4 = flat & 15;
            float4 a = *(const float4*)&g_ao[(size_t)(r0 + r) * DD + k0 + c4 * 4];
            As[c4*4+0][r] = a.x; As[c4*4+1][r] = a.y;
            As[c4*4+2][r] = a.z; As[c4*4+3][r] = a.w;
            float4 w = *(const float4*)&wp[(size_t)(c0 + r) * DD + k0 + c4 * 4];
            Ws[c4*4+0][r] = w.x; Ws[c4*4+1][r] = w.y;
            Ws[c4*4+2][r] = w.z; Ws[c4*4+3][r] = w.w;
        }
        __syncthreads();
#pragma unroll
        for (int kk = 0; kk < 64; kk++) {
            float a[4], b[4];
#pragma unroll
            for (int i = 0; i < 4; i++) a[i] = As[kk][ty * 4 + i];
#pragma unroll
            for (int j = 0; j < 4; j++) b[j] = Ws[kk][tx * 4 + j];
#pragma unroll
            for (int i = 0; i < 4; i++)
#pragma unroll
                for (int j = 0; j < 4; j++) acc[i][j] = fmaf(a[i], b[j], acc[i][j]);
        }
        __syncthreads();
    }
#pragma unroll
    for (int i = 0; i < 4; i++) {
        size_t off = (size_t)(r0 + ty * 4 + i) * DD + c0 + tx * 4;
        float4 xr = *(const float4*)&x[off];
        float4 r  = make_float4(acc[i][0] + xr.x, acc[i][1] + xr.y,
                                acc[i][2] + xr.z, acc[i][3] + xr.w);
        *(float4*)&out[off] = r;
    }
}

// ---------------------------------------------------------------- launch
extern "C" void kernel_launch(void* const* d_in, const int* in_sizes, int n_in,
                              void* d_out, int out_size) {
    const float* x     = (const float*)d_in[0];
    const float* Bb    = (const float*)d_in[1];
    const int*   M     = (const int*)  d_in[2];
    const float* gamma = (const float*)d_in[3];
    const float* beta  = (const float*)d_in[4];
    const float* wq    = (const float*)d_in[5];
    const float* wk    = (const float*)d_in[6];
    const float* wv    = (const float*)d_in[7];
    const float* wp    = (const float*)d_in[8];
    float* out = (float*)d_out;

    ln_kernel<<<NROWS, 128>>>(x, gamma, beta);
    qkv_kernel<<<dim3(NROWS / 64, NA, 3), 256>>>(wq, wk, wv);
    scores_kernel<<<dim3(THW / 64, THW / 64, NA * BSZ), 256>>>(Bb, M);
    softmax_kernel<<<NA * BSZ * THW, 256>>>();
    pv_kernel<<<dim3(THW / 64, NA * BSZ), 256>>>();
    proj_kernel<<<dim3(DD / 64, NROWS / 64), 256>>>(x, wp, out);
}

// round 2
// speedup vs baseline: 1.3140x; 1.3140x over previous
#include <cuda_runtime.h>
#include <cuda_bf16.h>

#define NA   8
#define BSZ  4
#define THW  1024
#define DD   512
#define DA   64
#define NROWS (BSZ*THW)   // 4096

// ---------------- device scratch (allocation forbidden) ----------------
__device__ __nv_bfloat16 g_xh[NROWS*DD], g_xl[NROWS*DD];          // normalized x hi/lo
__device__ __nv_bfloat16 g_qh[NA*NROWS*DA], g_ql[NA*NROWS*DA];    // q (pre-scaled 1/8)
__device__ __nv_bfloat16 g_kh[NA*NROWS*DA], g_kl[NA*NROWS*DA];
__device__ __nv_bfloat16 g_vth[NA*DA*NROWS], g_vtl[NA*DA*NROWS];  // v transposed [h][e][tok]
__device__ float g_s[33554432];                                    // scores/probs fp32 128MB
__device__ __nv_bfloat16 g_aoh[NROWS*DD], g_aol[NROWS*DD];        // concat attn out hi/lo

// ---------------- helpers ----------------
__device__ __forceinline__ void mma_bf16(float c[4], const unsigned a[4], const unsigned b[2]) {
    asm volatile(
        "mma.sync.aligned.m16n8k16.row.col.f32.bf16.bf16.f32 "
        "{%0,%1,%2,%3}, {%4,%5,%6,%7}, {%8,%9}, {%0,%1,%2,%3};\n"
        : "+f"(c[0]), "+f"(c[1]), "+f"(c[2]), "+f"(c[3])
        : "r"(a[0]), "r"(a[1]), "r"(a[2]), "r"(a[3]), "r"(b[0]), "r"(b[1]));
}

__device__ __forceinline__ void split1(float x, __nv_bfloat16& h, __nv_bfloat16& l) {
    h = __float2bfloat16_rn(x);
    l = __float2bfloat16_rn(x - __bfloat162float(h));
}

__device__ __forceinline__ void split_pair(float a, float b, unsigned& hi, unsigned& lo) {
    __nv_bfloat16 ah = __float2bfloat16_rn(a), bh = __float2bfloat16_rn(b);
    float ar = a - __bfloat162float(ah), br = b - __bfloat162float(bh);
    __nv_bfloat162 h2; h2.x = ah; h2.y = bh;
    __nv_bfloat162 l2; l2.x = __float2bfloat16_rn(ar); l2.y = __float2bfloat16_rn(br);
    hi = *reinterpret_cast<unsigned*>(&h2);
    lo = *reinterpret_cast<unsigned*>(&l2);
}

// One k16 MMA step for a 64x64 block tile with 4 warps (2x2, warp tile 32x32).
// Smem holds k-pairs-major tiles: T[kpair][m_or_n], padded ld=65.
// 3-MMA bf16 split: hi*hi + lo*hi + hi*lo.
__device__ __forceinline__ void compute_k16(
    const unsigned (*Ah)[65], const unsigned (*Al)[65],
    const unsigned (*Bh)[65], const unsigned (*Bl)[65],
    int s8, int mw, int nw, int g, int tg, float c[2][4][4])
{
    unsigned ah[2][4], al[2][4], bh[4][2], bl[4][2];
#pragma unroll
    for (int mi = 0; mi < 2; mi++) {
        int m = mw + mi*16 + g;
        ah[mi][0] = Ah[s8+tg][m];    ah[mi][1] = Ah[s8+tg][m+8];
        ah[mi][2] = Ah[s8+tg+4][m];  ah[mi][3] = Ah[s8+tg+4][m+8];
        al[mi][0] = Al[s8+tg][m];    al[mi][1] = Al[s8+tg][m+8];
        al[mi][2] = Al[s8+tg+4][m];  al[mi][3] = Al[s8+tg+4][m+8];
    }
#pragma unroll
    for (int ni = 0; ni < 4; ni++) {
        int n = nw + ni*8 + g;
        bh[ni][0] = Bh[s8+tg][n];  bh[ni][1] = Bh[s8+tg+4][n];
        bl[ni][0] = Bl[s8+tg][n];  bl[ni][1] = Bl[s8+tg+4][n];
    }
#pragma unroll
    for (int mi = 0; mi < 2; mi++)
#pragma unroll
        for (int ni = 0; ni < 4; ni++) {
            mma_bf16(c[mi][ni], ah[mi], bh[ni]);
            mma_bf16(c[mi][ni], al[mi], bh[ni]);
            mma_bf16(c[mi][ni], ah[mi], bl[ni]);
        }
}

// ---------------------------------------------------------------- LayerNorm
__global__ void ln_kernel(const float* __restrict__ x,
                          const float* __restrict__ gamma,
                          const float* __restrict__ beta) {
    int row = blockIdx.x;
    int t   = threadIdx.x;              // 128 threads
    const float* xr = x + (size_t)row * DD;
    float v[4];
    float s = 0.f;
#pragma unroll
    for (int i = 0; i < 4; i++) { v[i] = xr[i * 128 + t]; s += v[i]; }

    __shared__ float rbuf[4];
    __shared__ float stat;
#pragma unroll
    for (int o = 16; o > 0; o >>= 1) s += __shfl_xor_sync(0xffffffffu, s, o);
    if ((t & 31) == 0) rbuf[t >> 5] = s;
    __syncthreads();
    if (t == 0) stat = rbuf[0] + rbuf[1] + rbuf[2] + rbuf[3];
    __syncthreads();
    float mean = stat * (1.f / DD);

    float ss = 0.f;
#pragma unroll
    for (int i = 0; i < 4; i++) { float d = v[i] - mean; ss += d * d; }
    __syncthreads();
#pragma unroll
    for (int o = 16; o > 0; o >>= 1) ss += __shfl_xor_sync(0xffffffffu, ss, o);
    if ((t & 31) == 0) rbuf[t >> 5] = ss;
    __syncthreads();
    if (t == 0) stat = rbuf[0] + rbuf[1] + rbuf[2] + rbuf[3];
    __syncthreads();
    float rstd = rsqrtf(stat * (1.f / DD) + 1e-5f);

#pragma unroll
    for (int i = 0; i < 4; i++) {
        int c = i * 128 + t;
        float y = (v[i] - mean) * rstd * gamma[c] + beta[c];
        __nv_bfloat16 h, l; split1(y, h, l);
        g_xh[(size_t)row * DD + c] = h;
        g_xl[(size_t)row * DD + c] = l;
    }
}

// ---------------------------------------------------------------- QKV GEMM
// out[h][n][e] = sum_d xn[n][d] * w[h][d][e];  q additionally *1/8
__global__ __launch_bounds__(128) void qkv_kernel(const float* __restrict__ wq,
                                                  const float* __restrict__ wk,
                                                  const float* __restrict__ wv) {
    int h = blockIdx.y, which = blockIdx.z;
    const float* w = (which == 0) ? wq : ((which == 1) ? wk : wv);
    w += (size_t)h * DD * DA;
    int row0 = blockIdx.x * 64;

    __shared__ unsigned Ah[16][65], Al[16][65], Bh[16][65], Bl[16][65];
    int tid = threadIdx.x, lane = tid & 31, wid = tid >> 5;
    int g = lane >> 2, tg = lane & 3;
    int mw = (wid >> 1) * 32, nw = (wid & 1) * 32;
    float c[2][4][4] = {};

    for (int k0 = 0; k0 < DD; k0 += 32) {
        // A: xn hi/lo bf16 pairs (adjacent along k). 64 rows x 4 uint4 = 256 tasks.
#pragma unroll
        for (int it = 0; it < 2; it++) {
            int flat = it * 128 + tid;
            int r = flat >> 2, c4 = flat & 3;
            size_t off = (size_t)(row0 + r) * DD + k0 + c4 * 8;
            uint4 a = *(const uint4*)(g_xh + off);
            Ah[c4*4+0][r] = a.x; Ah[c4*4+1][r] = a.y; Ah[c4*4+2][r] = a.z; Ah[c4*4+3][r] = a.w;
            uint4 b = *(const uint4*)(g_xl + off);
            Al[c4*4+0][r] = b.x; Al[c4*4+1][r] = b.y; Al[c4*4+2][r] = b.z; Al[c4*4+3][r] = b.w;
        }
        // B: weights fp32 -> split & pack pairs across two k-rows. 16kp x 16 f4 = 256 tasks.
#pragma unroll
        for (int it = 0; it < 2; it++) {
            int flat = it * 128 + tid;
            int kp = flat >> 4, c4 = flat & 15;
            float4 r0v = *(const float4*)&w[(size_t)(k0 + 2*kp)     * DA + c4 * 4];
            float4 r1v = *(const float4*)&w[(size_t)(k0 + 2*kp + 1) * DA + c4 * 4];
            unsigned hi, lo;
            split_pair(r0v.x, r1v.x, hi, lo); Bh[kp][c4*4+0] = hi; Bl[kp][c4*4+0] = lo;
            split_pair(r0v.y, r1v.y, hi, lo); Bh[kp][c4*4+1] = hi; Bl[kp][c4*4+1] = lo;
            split_pair(r0v.z, r1v.z, hi, lo); Bh[kp][c4*4+2] = hi; Bl[kp][c4*4+2] = lo;
            split_pair(r0v.w, r1v.w, hi, lo); Bh[kp][c4*4+3] = hi; Bl[kp][c4*4+3] = lo;
        }
        __syncthreads();
#pragma unroll
        for (int s = 0; s < 2; s++) compute_k16(Ah, Al, Bh, Bl, s*8, mw, nw, g, tg, c);
        __syncthreads();
    }

    float scale = (which == 0) ? 0.125f : 1.0f;
#pragma unroll
    for (int mi = 0; mi < 2; mi++)
#pragma unroll
        for (int ni = 0; ni < 4; ni++) {
            int gr = row0 + mw + mi*16 + g;
            int cb = nw + ni*8 + 2*tg;
            float v0 = c[mi][ni][0]*scale, v1 = c[mi][ni][1]*scale;
            float v2 = c[mi][ni][2]*scale, v3 = c[mi][ni][3]*scale;
            if (which == 2) {
                __nv_bfloat16 hh, ll;
                split1(v0, hh, ll);
                g_vth[(size_t)(h*DA + cb)  *NROWS + gr]   = hh; g_vtl[(size_t)(h*DA + cb)  *NROWS + gr]   = ll;
                split1(v1, hh, ll);
                g_vth[(size_t)(h*DA + cb+1)*NROWS + gr]   = hh; g_vtl[(size_t)(h*DA + cb+1)*NROWS + gr]   = ll;
                split1(v2, hh, ll);
                g_vth[(size_t)(h*DA + cb)  *NROWS + gr+8] = hh; g_vtl[(size_t)(h*DA + cb)  *NROWS + gr+8] = ll;
                split1(v3, hh, ll);
                g_vth[(size_t)(h*DA + cb+1)*NROWS + gr+8] = hh; g_vtl[(size_t)(h*DA + cb+1)*NROWS + gr+8] = ll;
            } else {
                __nv_bfloat16* oh = (which == 0) ? g_qh : g_kh;
                __nv_bfloat16* ol = (which == 0) ? g_ql : g_kl;
                unsigned hi, lo;
                split_pair(v0, v1, hi, lo);
                *(unsigned*)(oh + (size_t)(h*NROWS + gr)*DA + cb) = hi;
                *(unsigned*)(ol + (size_t)(h*NROWS + gr)*DA + cb) = lo;
                split_pair(v2, v3, hi, lo);
                *(unsigned*)(oh + (size_t)(h*NROWS + gr+8)*DA + cb) = hi;
                *(unsigned*)(ol + (size_t)(h*NROWS + gr+8)*DA + cb) = lo;
            }
        }
}

// ------------------------------------------------- scores = qk^T + bias, mask
__global__ __launch_bounds__(128) void scores_kernel(const float* __restrict__ Bb,
                                                     const int* __restrict__ M) {
    int hb = blockIdx.z;
    int h = hb >> 2, b = hb & 3;
    size_t qko = ((size_t)h * NROWS + (size_t)b * THW) * DA;
    int qr0 = blockIdx.y * 64, kc0 = blockIdx.x * 64;

    __shared__ unsigned Qh[32][65], Ql[32][65], Kh[32][65], Kl[32][65];
    int tid = threadIdx.x, lane = tid & 31, wid = tid >> 5;
    int g = lane >> 2, tg = lane & 3;
    int mw = (wid >> 1) * 32, nw = (wid & 1) * 32;

    // 64 rows x 8 uint4 = 512 tasks each side
#pragma unroll
    for (int it = 0; it < 4; it++) {
        int flat = it * 128 + tid;
        int r = flat >> 3, c4 = flat & 7;
        size_t qoff = qko + (size_t)(qr0 + r) * DA + c4 * 8;
        uint4 a = *(const uint4*)(g_qh + qoff);
        Qh[c4*4+0][r] = a.x; Qh[c4*4+1][r] = a.y; Qh[c4*4+2][r] = a.z; Qh[c4*4+3][r] = a.w;
        uint4 b2 = *(const uint4*)(g_ql + qoff);
        Ql[c4*4+0][r] = b2.x; Ql[c4*4+1][r] = b2.y; Ql[c4*4+2][r] = b2.z; Ql[c4*4+3][r] = b2.w;
        size_t koff = qko + (size_t)(kc0 + r) * DA + c4 * 8;
        uint4 e = *(const uint4*)(g_kh + koff);
        Kh[c4*4+0][r] = e.x; Kh[c4*4+1][r] = e.y; Kh[c4*4+2][r] = e.z; Kh[c4*4+3][r] = e.w;
        uint4 f = *(const uint4*)(g_kl + koff);
        Kl[c4*4+0][r] = f.x; Kl[c4*4+1][r] = f.y; Kl[c4*4+2][r] = f.z; Kl[c4*4+3][r] = f.w;
    }
    __syncthreads();

    float c[2][4][4] = {};
#pragma unroll
    for (int s = 0; s < 4; s++) compute_k16(Qh, Ql, Kh, Kl, s*8, mw, nw, g, tg, c);

    size_t Sbase = (size_t)hb * THW * THW;
#pragma unroll
    for (int mi = 0; mi < 2; mi++)
#pragma unroll
        for (int ni = 0; ni < 4; ni++) {
            int q   = qr0 + mw + mi*16 + g;
            int col = kc0 + nw + ni*8 + 2*tg;
#pragma unroll
            for (int rr = 0; rr < 2; rr++) {
                size_t moff = (size_t)(q + rr*8) * THW + col;
                size_t off  = Sbase + moff;
                float2 bb = *(const float2*)&Bb[off];
                int2   mm = *(const int2*)&M[moff];
                float2 r;
                r.x = mm.x ? -10000.f : c[mi][ni][rr*2+0] + bb.x;
                r.y = mm.y ? -10000.f : c[mi][ni][rr*2+1] + bb.y;
                *(float2*)&g_s[off] = r;
            }
        }
}

// ---------------------------------------------------------------- softmax
__global__ void softmax_kernel() {
    float* S = g_s + (size_t)blockIdx.x * THW;
    int t = threadIdx.x;            // 256 threads, 4 elems each
    float4 v = *(float4*)&S[t * 4];
    float m = fmaxf(fmaxf(v.x, v.y), fmaxf(v.z, v.w));
    __shared__ float rbuf[8];
    __shared__ float stat;
#pragma unroll
    for (int o = 16; o > 0; o >>= 1) m = fmaxf(m, __shfl_xor_sync(0xffffffffu, m, o));
    if ((t & 31) == 0) rbuf[t >> 5] = m;
    __syncthreads();
    if (t == 0) {
        float mm = rbuf[0];
#pragma unroll
        for (int i = 1; i < 8; i++) mm = fmaxf(mm, rbuf[i]);
        stat = mm;
    }
    __syncthreads();
    m = stat;
    v.x = __expf(v.x - m); v.y = __expf(v.y - m);
    v.z = __expf(v.z - m); v.w = __expf(v.w - m);
    float s = v.x + v.y + v.z + v.w;
    __syncthreads();
#pragma unroll
    for (int o = 16; o > 0; o >>= 1) s += __shfl_xor_sync(0xffffffffu, s, o);
    if ((t & 31) == 0) rbuf[t >> 5] = s;
    __syncthreads();
    if (t == 0) {
        float ss = 0.f;
#pragma unroll
        for (int i = 0; i < 8; i++) ss += rbuf[i];
        stat = ss;
    }
    __syncthreads();
    float inv = 1.f / stat;
    v.x *= inv; v.y *= inv; v.z *= inv; v.w *= inv;
    *(float4*)&S[t * 4] = v;
}

// ---------------------------------------------------------------- PV GEMM
__global__ __launch_bounds__(128) void pv_kernel() {
    int hb = blockIdx.y;
    int h = hb >> 2, b = hb & 3;
    const float* P = g_s + (size_t)hb * THW * THW;
    int qr0 = blockIdx.x * 64;

    __shared__ unsigned Ph[16][65], Pl[16][65], Vh[16][65], Vl[16][65];
    int tid = threadIdx.x, lane = tid & 31, wid = tid >> 5;
    int g = lane >> 2, tg = lane & 3;
    int mw = (wid >> 1) * 32, nw = (wid & 1) * 32;
    float c[2][4][4] = {};

    for (int t0 = 0; t0 < THW; t0 += 32) {
        // A: P fp32 -> split/pack. 64 rows x 8 float4 = 512 tasks.
#pragma unroll
        for (int it = 0; it < 4; it++) {
            int flat = it * 128 + tid;
            int r = flat >> 3, c4 = flat & 7;
            float4 p = *(const float4*)&P[(size_t)(qr0 + r) * THW + t0 + c4 * 4];
            unsigned h0, l0, h1, l1;
            split_pair(p.x, p.y, h0, l0);
            split_pair(p.z, p.w, h1, l1);
            Ph[c4*2][r] = h0; Ph[c4*2+1][r] = h1;
            Pl[c4*2][r] = l0; Pl[c4*2+1][r] = l1;
        }
        // B: v transposed bf16 pairs along t. 64 e-rows x 4 uint4 = 256 tasks.
#pragma unroll
        for (int it = 0; it < 2; it++) {
            int flat = it * 128 + tid;
            int e = flat >> 2, c4 = flat & 3;
            size_t base = (size_t)(h*DA + e) * NROWS + b*THW + t0 + c4*8;
            uint4 a = *(const uint4*)(g_vth + base);
            Vh[c4*4+0][e] = a.x; Vh[c4*4+1][e] = a.y; Vh[c4*4+2][e] = a.z; Vh[c4*4+3][e] = a.w;
            uint4 b2 = *(const uint4*)(g_vtl + base);
            Vl[c4*4+0][e] = b2.x; Vl[c4*4+1][e] = b2.y; Vl[c4*4+2][e] = b2.z; Vl[c4*4+3][e] = b2.w;
        }
        __syncthreads();
#pragma unroll
        for (int s = 0; s < 2; s++) compute_k16(Ph, Pl, Vh, Vl, s*8, mw, nw, g, tg, c);
        __syncthreads();
    }

#pragma unroll
    for (int mi = 0; mi < 2; mi++)
#pragma unroll
        for (int ni = 0; ni < 4; ni++) {
            int tok = b*THW + qr0 + mw + mi*16 + g;
            int col = h*DA + nw + ni*8 + 2*tg;
            unsigned hi, lo;
            split_pair(c[mi][ni][0], c[mi][ni][1], hi, lo);
            *(unsigned*)(g_aoh + (size_t)tok * DD + col) = hi;
            *(unsigned*)(g_aol + (size_t)tok * DD + col) = lo;
            split_pair(c[mi][ni][2], c[mi][ni][3], hi, lo);
            *(unsigned*)(g_aoh + (size_t)(tok+8) * DD + col) = hi;
            *(unsigned*)(g_aol + (size_t)(tok+8) * DD + col) = lo;
        }
}

// ------------------------------------------------- proj + residual
// y[n][o] = sum_i ao[n][i] * wp[o][i] + x[n][o]
__global__ __launch_bounds__(128) void proj_kernel(const float* __restrict__ x,
                                                   const float* __restrict__ wp,
                                                   float* __restrict__ out) {
    int r0 = blockIdx.y * 64, c0 = blockIdx.x * 64;
    __shared__ unsigned Ah[16][65], Al[16][65], Bh[16][65], Bl[16][65];
    int tid = threadIdx.x, lane = tid & 31, wid = tid >> 5;
    int g = lane >> 2, tg = lane & 3;
    int mw = (wid >> 1) * 32, nw = (wid & 1) * 32;
    float c[2][4][4] = {};

    for (int k0 = 0; k0 < DD; k0 += 32) {
        // A: ao hi/lo bf16. 64 rows x 4 uint4 = 256 tasks.
#pragma unroll
        for (int it = 0; it < 2; it++) {
            int flat = it * 128 + tid;
            int r = flat >> 2, c4 = flat & 3;
            size_t off = (size_t)(r0 + r) * DD + k0 + c4 * 8;
            uint4 a = *(const uint4*)(g_aoh + off);
            Ah[c4*4+0][r] = a.x; Ah[c4*4+1][r] = a.y; Ah[c4*4+2][r] = a.z; Ah[c4*4+3][r] = a.w;
            uint4 b = *(const uint4*)(g_aol + off);
            Al[c4*4+0][r] = b.x; Al[c4*4+1][r] = b.y; Al[c4*4+2][r] = b.z; Al[c4*4+3][r] = b.w;
        }
        // B: wp fp32 [o][i], i contiguous. 64 o-rows x 8 float4 = 512 tasks.
#pragma unroll
        for (int it = 0; it < 4; it++) {
            int flat = it * 128 + tid;
            int o = flat >> 3, c4 = flat & 7;
            float4 wv = *(const float4*)&wp[(size_t)(c0 + o) * DD + k0 + c4 * 4];
            unsigned h0, l0, h1, l1;
            split_pair(wv.x, wv.y, h0, l0);
            split_pair(wv.z, wv.w, h1, l1);
            Bh[c4*2][o] = h0; Bh[c4*2+1][o] = h1;
            Bl[c4*2][o] = l0; Bl[c4*2+1][o] = l1;
        }
        __syncthreads();
#pragma unroll
        for (int s = 0; s < 2; s++) compute_k16(Ah, Al, Bh, Bl, s*8, mw, nw, g, tg, c);
        __syncthreads();
    }

#pragma unroll
    for (int mi = 0; mi < 2; mi++)
#pragma unroll
        for (int ni = 0; ni < 4; ni++) {
            int row = r0 + mw + mi*16 + g;
            int col = c0 + nw + ni*8 + 2*tg;
#pragma unroll
            for (int rr = 0; rr < 2; rr++) {
                size_t off = (size_t)(row + rr*8) * DD + col;
                float2 xr = *(const float2*)&x[off];
                float2 r;
                r.x = c[mi][ni][rr*2+0] + xr.x;
                r.y = c[mi][ni][rr*2+1] + xr.y;
                *(float2*)&out[off] = r;
            }
        }
}

// ---------------------------------------------------------------- launch
extern "C" void kernel_launch(void* const* d_in, const int* in_sizes, int n_in,
                              void* d_out, int out_size) {
    const float* x     = (const float*)d_in[0];
    const float* Bb    = (const float*)d_in[1];
    const int*   M     = (const int*)  d_in[2];
    const float* gamma = (const float*)d_in[3];
    const float* beta  = (const float*)d_in[4];
    const float* wq    = (const float*)d_in[5];
    const float* wk    = (const float*)d_in[6];
    const float* wv    = (const float*)d_in[7];
    const float* wp    = (const float*)d_in[8];
    float* out = (float*)d_out;

    ln_kernel<<<NROWS, 128>>>(x, gamma, beta);
    qkv_kernel<<<dim3(NROWS / 64, NA, 3), 128>>>(wq, wk, wv);
    scores_kernel<<<dim3(THW / 64, THW / 64, NA * BSZ), 128>>>(Bb, M);
    softmax_kernel<<<NA * BSZ * THW, 256>>>();
    pv_kernel<<<dim3(THW / 64, NA * BSZ), 128>>>();
    proj_kernel<<<dim3(DD / 64, NROWS / 64), 128>>>(x, wp, out);
}

// round 4
// speedup vs baseline: 1.9208x; 1.4617x over previous
#include <cuda_runtime.h>
#include <cuda_bf16.h>

#define NA   8
#define BSZ  4
#define THW  1024
#define DD   512
#define DA   64
#define NROWS (BSZ*THW)   // 4096

// ---------------- device scratch (allocation forbidden) ----------------
__device__ __nv_bfloat16 g_xh[NROWS*DD], g_xl[NROWS*DD];          // normalized x hi/lo
__device__ __nv_bfloat16 g_qh[NA*NROWS*DA], g_ql[NA*NROWS*DA];    // q (pre-scaled 1/8)
__device__ __nv_bfloat16 g_kh[NA*NROWS*DA], g_kl[NA*NROWS*DA];
__device__ __nv_bfloat16 g_vh[NA*NROWS*DA], g_vl[NA*NROWS*DA];    // v row-major
__device__ __nv_bfloat16 g_aoh[NROWS*DD], g_aol[NROWS*DD];        // concat attn out hi/lo

// ---------------- helpers ----------------
__device__ __forceinline__ void mma_bf16(float c[4], const unsigned a[4], const unsigned b[2]) {
    asm volatile(
        "mma.sync.aligned.m16n8k16.row.col.f32.bf16.bf16.f32 "
        "{%0,%1,%2,%3}, {%4,%5,%6,%7}, {%8,%9}, {%0,%1,%2,%3};\n"
        : "+f"(c[0]), "+f"(c[1]), "+f"(c[2]), "+f"(c[3])
        : "r"(a[0]), "r"(a[1]), "r"(a[2]), "r"(a[3]), "r"(b[0]), "r"(b[1]));
}

__device__ __forceinline__ void mma4(float c[4], const unsigned a[4], unsigned b0, unsigned b1) {
    asm volatile(
        "mma.sync.aligned.m16n8k16.row.col.f32.bf16.bf16.f32 "
        "{%0,%1,%2,%3}, {%4,%5,%6,%7}, {%8,%9}, {%0,%1,%2,%3};\n"
        : "+f"(c[0]), "+f"(c[1]), "+f"(c[2]), "+f"(c[3])
        : "r"(a[0]), "r"(a[1]), "r"(a[2]), "r"(a[3]), "r"(b0), "r"(b1));
}

__device__ __forceinline__ void ldsm4(unsigned& r0, unsigned& r1, unsigned& r2, unsigned& r3,
                                      const void* p) {
    unsigned addr = (unsigned)__cvta_generic_to_shared(p);
    asm volatile("ldmatrix.sync.aligned.m8n8.x4.shared.b16 {%0,%1,%2,%3}, [%4];"
                 : "=r"(r0), "=r"(r1), "=r"(r2), "=r"(r3) : "r"(addr));
}

__device__ __forceinline__ void ldsm4t(unsigned& r0, unsigned& r1, unsigned& r2, unsigned& r3,
                                       const void* p) {
    unsigned addr = (unsigned)__cvta_generic_to_shared(p);
    asm volatile("ldmatrix.sync.aligned.m8n8.x4.trans.shared.b16 {%0,%1,%2,%3}, [%4];"
                 : "=r"(r0), "=r"(r1), "=r"(r2), "=r"(r3) : "r"(addr));
}

__device__ __forceinline__ void split1(float x, __nv_bfloat16& h, __nv_bfloat16& l) {
    h = __float2bfloat16_rn(x);
    l = __float2bfloat16_rn(x - __bfloat162float(h));
}

__device__ __forceinline__ void split_pair(float a, float b, unsigned& hi, unsigned& lo) {
    __nv_bfloat16 ah = __float2bfloat16_rn(a), bh = __float2bfloat16_rn(b);
    float ar = a - __bfloat162float(ah), br = b - __bfloat162float(bh);
    __nv_bfloat162 h2; h2.x = ah; h2.y = bh;
    __nv_bfloat162 l2; l2.x = __float2bfloat16_rn(ar); l2.y = __float2bfloat16_rn(br);
    hi = *reinterpret_cast<unsigned*>(&h2);
    lo = *reinterpret_cast<unsigned*>(&l2);
}

// 64x64 bf16 tile, 128B rows, 16B-chunk swizzle: chunk ^= (row & 7)
__device__ __forceinline__ void load_tile(char* dst, const __nv_bfloat16* src, int tid) {
#pragma unroll
    for (int it = 0; it < 4; it++) {
        int flat = it * 128 + tid;
        int r = flat >> 3, c = flat & 7;
        uint4 v = *(const uint4*)(src + (size_t)r * 64 + c * 8);
        *(uint4*)(dst + r * 128 + ((c ^ (r & 7)) << 4)) = v;
    }
}

// ---------------------------------------------------------------- LayerNorm
__global__ void ln_kernel(const float* __restrict__ x,
                          const float* __restrict__ gamma,
                          const float* __restrict__ beta) {
    int row = blockIdx.x;
    int t   = threadIdx.x;              // 128 threads
    const float* xr = x + (size_t)row * DD;
    float v[4];
    float s = 0.f;
#pragma unroll
    for (int i = 0; i < 4; i++) { v[i] = xr[i * 128 + t]; s += v[i]; }

    __shared__ float rbuf[4];
    __shared__ float stat;
#pragma unroll
    for (int o = 16; o > 0; o >>= 1) s += __shfl_xor_sync(0xffffffffu, s, o);
    if ((t & 31) == 0) rbuf[t >> 5] = s;
    __syncthreads();
    if (t == 0) stat = rbuf[0] + rbuf[1] + rbuf[2] + rbuf[3];
    __syncthreads();
    float mean = stat * (1.f / DD);

    float ss = 0.f;
#pragma unroll
    for (int i = 0; i < 4; i++) { float d = v[i] - mean; ss += d * d; }
    __syncthreads();
#pragma unroll
    for (int o = 16; o > 0; o >>= 1) ss += __shfl_xor_sync(0xffffffffu, ss, o);
    if ((t & 31) == 0) rbuf[t >> 5] = ss;
    __syncthreads();
    if (t == 0) stat = rbuf[0] + rbuf[1] + rbuf[2] + rbuf[3];
    __syncthreads();
    float rstd = rsqrtf(stat * (1.f / DD) + 1e-5f);

#pragma unroll
    for (int i = 0; i < 4; i++) {
        int c = i * 128 + t;
        float y = (v[i] - mean) * rstd * gamma[c] + beta[c];
        __nv_bfloat16 h, l; split1(y, h, l);
        g_xh[(size_t)row * DD + c] = h;
        g_xl[(size_t)row * DD + c] = l;
    }
}

// One k16 MMA step, 64x64 block tile, 4 warps (2x2 of 32x32), legacy smem layout.
__device__ __forceinline__ void compute_k16(
    const unsigned (*Ah)[65], const unsigned (*Al)[65],
    const unsigned (*Bh)[65], const unsigned (*Bl)[65],
    int s8, int mw, int nw, int g, int tg, float c[2][4][4])
{
    unsigned ah[2][4], al[2][4], bh[4][2], bl[4][2];
#pragma unroll
    for (int mi = 0; mi < 2; mi++) {
        int m = mw + mi*16 + g;
        ah[mi][0] = Ah[s8+tg][m];    ah[mi][1] = Ah[s8+tg][m+8];
        ah[mi][2] = Ah[s8+tg+4][m];  ah[mi][3] = Ah[s8+tg+4][m+8];
        al[mi][0] = Al[s8+tg][m];    al[mi][1] = Al[s8+tg][m+8];
        al[mi][2] = Al[s8+tg+4][m];  al[mi][3] = Al[s8+tg+4][m+8];
    }
#pragma unroll
    for (int ni = 0; ni < 4; ni++) {
        int n = nw + ni*8 + g;
        bh[ni][0] = Bh[s8+tg][n];  bh[ni][1] = Bh[s8+tg+4][n];
        bl[ni][0] = Bl[s8+tg][n];  bl[ni][1] = Bl[s8+tg+4][n];
    }
#pragma unroll
    for (int mi = 0; mi < 2; mi++)
#pragma unroll
        for (int ni = 0; ni < 4; ni++) {
            mma_bf16(c[mi][ni], ah[mi], bh[ni]);
            mma_bf16(c[mi][ni], al[mi], bh[ni]);
            mma_bf16(c[mi][ni], ah[mi], bl[ni]);
        }
}

// ---------------------------------------------------------------- QKV GEMM
// out[h][n][e] = sum_d xn[n][d] * w[h][d][e];  q additionally *1/8
__global__ __launch_bounds__(128) void qkv_kernel(const float* __restrict__ wq,
                                                  const float* __restrict__ wk,
                                                  const float* __restrict__ wv) {
    int h = blockIdx.y, which = blockIdx.z;
    const float* w = (which == 0) ? wq : ((which == 1) ? wk : wv);
    w += (size_t)h * DD * DA;
    int row0 = blockIdx.x * 64;

    __shared__ unsigned Ah[16][65], Al[16][65], Bh[16][65], Bl[16][65];
    int tid = threadIdx.x, lane = tid & 31, wid = tid >> 5;
    int g = lane >> 2, tg = lane & 3;
    int mw = (wid >> 1) * 32, nw = (wid & 1) * 32;
    float c[2][4][4] = {};

    for (int k0 = 0; k0 < DD; k0 += 32) {
#pragma unroll
        for (int it = 0; it < 2; it++) {
            int flat = it * 128 + tid;
            int r = flat >> 2, c4 = flat & 3;
            size_t off = (size_t)(row0 + r) * DD + k0 + c4 * 8;
            uint4 a = *(const uint4*)(g_xh + off);
            Ah[c4*4+0][r] = a.x; Ah[c4*4+1][r] = a.y; Ah[c4*4+2][r] = a.z; Ah[c4*4+3][r] = a.w;
            uint4 b = *(const uint4*)(g_xl + off);
            Al[c4*4+0][r] = b.x; Al[c4*4+1][r] = b.y; Al[c4*4+2][r] = b.z; Al[c4*4+3][r] = b.w;
        }
#pragma unroll
        for (int it = 0; it < 2; it++) {
            int flat = it * 128 + tid;
            int kp = flat >> 4, c4 = flat & 15;
            float4 r0v = *(const float4*)&w[(size_t)(k0 + 2*kp)     * DA + c4 * 4];
            float4 r1v = *(const float4*)&w[(size_t)(k0 + 2*kp + 1) * DA + c4 * 4];
            unsigned hi, lo;
            split_pair(r0v.x, r1v.x, hi, lo); Bh[kp][c4*4+0] = hi; Bl[kp][c4*4+0] = lo;
            split_pair(r0v.y, r1v.y, hi, lo); Bh[kp][c4*4+1] = hi; Bl[kp][c4*4+1] = lo;
            split_pair(r0v.z, r1v.z, hi, lo); Bh[kp][c4*4+2] = hi; Bl[kp][c4*4+2] = lo;
            split_pair(r0v.w, r1v.w, hi, lo); Bh[kp][c4*4+3] = hi; Bl[kp][c4*4+3] = lo;
        }
        __syncthreads();
#pragma unroll
        for (int s = 0; s < 2; s++) compute_k16(Ah, Al, Bh, Bl, s*8, mw, nw, g, tg, c);
        __syncthreads();
    }

    float scale = (which == 0) ? 0.125f : 1.0f;
    __nv_bfloat16* oh = (which == 0) ? g_qh : ((which == 1) ? g_kh : g_vh);
    __nv_bfloat16* ol = (which == 0) ? g_ql : ((which == 1) ? g_kl : g_vl);
#pragma unroll
    for (int mi = 0; mi < 2; mi++)
#pragma unroll
        for (int ni = 0; ni < 4; ni++) {
            int gr = row0 + mw + mi*16 + g;
            int cb = nw + ni*8 + 2*tg;
            unsigned hi, lo;
            split_pair(c[mi][ni][0]*scale, c[mi][ni][1]*scale, hi, lo);
            *(unsigned*)(oh + (size_t)(h*NROWS + gr)*DA + cb) = hi;
            *(unsigned*)(ol + (size_t)(h*NROWS + gr)*DA + cb) = lo;
            split_pair(c[mi][ni][2]*scale, c[mi][ni][3]*scale, hi, lo);
            *(unsigned*)(oh + (size_t)(h*NROWS + gr+8)*DA + cb) = hi;
            *(unsigned*)(ol + (size_t)(h*NROWS + gr+8)*DA + cb) = lo;
        }
}

// ---------------------------------------------------------------- fused attention
// grid (THW/64, NA*BSZ), 128 threads (4 warps, m16 each)
__global__ __launch_bounds__(128) void attn_kernel(const float* __restrict__ Bb,
                                                   const int* __restrict__ M) {
    int hb = blockIdx.y;
    int h = hb >> 2, b = hb & 3;
    int qr0 = blockIdx.x * 64;

    __shared__ __align__(16) char sm[4 * 8192];
    char* Kh = sm;
    char* Kl = sm + 8192;
    char* Vh = sm + 16384;
    char* Vl = sm + 24576;

    int tid = threadIdx.x, lane = tid & 31, wid = tid >> 5;
    int g = lane >> 2, tg = lane & 3;
    int mw = wid * 16;
    int grp = lane >> 3, li = lane & 7;

    size_t kv_base = (size_t)(h * NROWS + b * THW) * DA;

    // ---- load Q tile into Kh/Kl, extract A-frags to registers ----
    load_tile(Kh, g_qh + kv_base + (size_t)qr0 * DA, tid);
    load_tile(Kl, g_ql + kv_base + (size_t)qr0 * DA, tid);
    __syncthreads();
    unsigned qfh[4][4], qfl[4][4];
    {
        int qrow = mw + ((grp & 1) << 3) + li;
        int q7 = qrow & 7;
#pragma unroll
        for (int s4 = 0; s4 < 4; s4++) {
            int ch = s4 * 2 + (grp >> 1);
            const char* ph = Kh + qrow * 128 + ((ch ^ q7) << 4);
            const char* pl = Kl + qrow * 128 + ((ch ^ q7) << 4);
            ldsm4(qfh[s4][0], qfh[s4][1], qfh[s4][2], qfh[s4][3], ph);
            ldsm4(qfl[s4][0], qfl[s4][1], qfl[s4][2], qfl[s4][3], pl);
        }
    }
    __syncthreads();

    float m0 = -1e30f, m1 = -1e30f, l0 = 0.f, l1 = 0.f;
    float O[8][4] = {};

    // per-thread fixed address components
    int krow[4];
#pragma unroll
    for (int jp = 0; jp < 4; jp++) krow[jp] = 16 * jp + ((grp >> 1) << 3) + li;
    int vrow_b = ((grp & 1) << 3) + li;

    const float* Brow = Bb + ((size_t)hb * THW + (qr0 + mw + g)) * THW + 2 * tg;
    const int*   Mrow = M  + (size_t)(qr0 + mw + g) * THW + 2 * tg;

    for (int kt = 0; kt < 16; kt++) {
        load_tile(Kh, g_kh + kv_base + (size_t)(kt * 64) * DA, tid);
        load_tile(Kl, g_kl + kv_base + (size_t)(kt * 64) * DA, tid);
        load_tile(Vh, g_vh + kv_base + (size_t)(kt * 64) * DA, tid);
        load_tile(Vl, g_vl + kv_base + (size_t)(kt * 64) * DA, tid);
        __syncthreads();

        // ---- S = Q K^T (3-MMA split) ----
        float sc[8][4] = {};
#pragma unroll
        for (int s4 = 0; s4 < 4; s4++) {
#pragma unroll
            for (int jp = 0; jp < 4; jp++) {
                int rr = krow[jp];
                int sw = ((s4 * 2 + (grp & 1)) ^ (rr & 7)) << 4;
                unsigned h0, h1, h2, h3, e0, e1, e2, e3;
                ldsm4(h0, h1, h2, h3, Kh + rr * 128 + sw);
                ldsm4(e0, e1, e2, e3, Kl + rr * 128 + sw);
                mma4(sc[2*jp],   qfh[s4], h0, h1);
                mma4(sc[2*jp],   qfl[s4], h0, h1);
                mma4(sc[2*jp],   qfh[s4], e0, e1);
                mma4(sc[2*jp+1], qfh[s4], h2, h3);
                mma4(sc[2*jp+1], qfl[s4], h2, h3);
                mma4(sc[2*jp+1], qfh[s4], e2, e3);
            }
        }

        // ---- bias + mask ----
        const float* Bp = Brow + (size_t)kt * 64;
        const int*   Mp = Mrow + kt * 64;
#pragma unroll
        for (int j = 0; j < 8; j++) {
            float2 b0 = *(const float2*)(Bp + j * 8);
            int2   i0 = *(const int2*)  (Mp + j * 8);
            sc[j][0] = i0.x ? -10000.f : sc[j][0] + b0.x;
            sc[j][1] = i0.y ? -10000.f : sc[j][1] + b0.y;
            float2 b1 = *(const float2*)(Bp + 8 * THW + j * 8);
            int2   i1 = *(const int2*)  (Mp + 8 * THW + j * 8);
            sc[j][2] = i1.x ? -10000.f : sc[j][2] + b1.x;
            sc[j][3] = i1.y ? -10000.f : sc[j][3] + b1.y;
        }

        // ---- online softmax update ----
        float rm0 = -1e30f, rm1 = -1e30f;
#pragma unroll
        for (int j = 0; j < 8; j++) {
            rm0 = fmaxf(rm0, fmaxf(sc[j][0], sc[j][1]));
            rm1 = fmaxf(rm1, fmaxf(sc[j][2], sc[j][3]));
        }
        rm0 = fmaxf(rm0, __shfl_xor_sync(0xffffffffu, rm0, 1));
        rm0 = fmaxf(rm0, __shfl_xor_sync(0xffffffffu, rm0, 2));
        rm1 = fmaxf(rm1, __shfl_xor_sync(0xffffffffu, rm1, 1));
        rm1 = fmaxf(rm1, __shfl_xor_sync(0xffffffffu, rm1, 2));
        float nm0 = fmaxf(m0, rm0), nm1 = fmaxf(m1, rm1);
        float a0 = __expf(m0 - nm0), a1 = __expf(m1 - nm1);
        float ls0 = 0.f, ls1 = 0.f;
#pragma unroll
        for (int j = 0; j < 8; j++) {
            sc[j][0] = __expf(sc[j][0] - nm0); ls0 += sc[j][0];
            sc[j][1] = __expf(sc[j][1] - nm0); ls0 += sc[j][1];
            sc[j][2] = __expf(sc[j][2] - nm1); ls1 += sc[j][2];
            sc[j][3] = __expf(sc[j][3] - nm1); ls1 += sc[j][3];
        }
        ls0 += __shfl_xor_sync(0xffffffffu, ls0, 1);
        ls0 += __shfl_xor_sync(0xffffffffu, ls0, 2);
        ls1 += __shfl_xor_sync(0xffffffffu, ls1, 1);
        ls1 += __shfl_xor_sync(0xffffffffu, ls1, 2);
        l0 = l0 * a0 + ls0;
        l1 = l1 * a1 + ls1;
        m0 = nm0; m1 = nm1;
#pragma unroll
        for (int j = 0; j < 8; j++) {
            O[j][0] *= a0; O[j][1] *= a0;
            O[j][2] *= a1; O[j][3] *= a1;
        }

        // ---- O += P V (P from registers, 3-MMA split) ----
#pragma unroll
        for (int t = 0; t < 4; t++) {
            unsigned ph[4], pl[4];
            split_pair(sc[2*t][0],   sc[2*t][1],   ph[0], pl[0]);
            split_pair(sc[2*t][2],   sc[2*t][3],   ph[1], pl[1]);
            split_pair(sc[2*t+1][0], sc[2*t+1][1], ph[2], pl[2]);
            split_pair(sc[2*t+1][2], sc[2*t+1][3], ph[3], pl[3]);
            int rr = 16 * t + vrow_b;
            int r7 = rr & 7;
#pragma unroll
            for (int jp = 0; jp < 4; jp++) {
                int sw = ((2 * jp + (grp >> 1)) ^ r7) << 4;
                unsigned h0, h1, h2, h3, e0, e1, e2, e3;
                ldsm4t(h0, h1, h2, h3, Vh + rr * 128 + sw);
                ldsm4t(e0, e1, e2, e3, Vl + rr * 128 + sw);
                mma4(O[2*jp],   ph, h0, h1);
                mma4(O[2*jp],   pl, h0, h1);
                mma4(O[2*jp],   ph, e0, e1);
                mma4(O[2*jp+1], ph, h2, h3);
                mma4(O[2*jp+1], pl, h2, h3);
                mma4(O[2*jp+1], ph, e2, e3);
            }
        }
        __syncthreads();
    }

    // ---- normalize + write (bf16 hi/lo for proj) ----
    float inv0 = 1.f / l0, inv1 = 1.f / l1;
    int tok0 = b * THW + qr0 + mw + g;
#pragma unroll
    for (int j = 0; j < 8; j++) {
        int col = h * DA + j * 8 + 2 * tg;
        unsigned hi, lo;
        split_pair(O[j][0] * inv0, O[j][1] * inv0, hi, lo);
        *(unsigned*)(g_aoh + (size_t)tok0 * DD + col) = hi;
        *(unsigned*)(g_aol + (size_t)tok0 * DD + col) = lo;
        split_pair(O[j][2] * inv1, O[j][3] * inv1, hi, lo);
        *(unsigned*)(g_aoh + (size_t)(tok0 + 8) * DD + col) = hi;
        *(unsigned*)(g_aol + (size_t)(tok0 + 8) * DD + col) = lo;
    }
}

// ------------------------------------------------- proj + residual
__global__ __launch_bounds__(128) void proj_kernel(const float* __restrict__ x,
                                                   const float* __restrict__ wp,
                                                   float* __restrict__ out) {
    int r0 = blockIdx.y * 64, c0 = blockIdx.x * 64;
    __shared__ unsigned Ah[16][65], Al[16][65], Bh[16][65], Bl[16][65];
    int tid = threadIdx.x, lane = tid & 31, wid = tid >> 5;
    int g = lane >> 2, tg = lane & 3;
    int mw = (wid >> 1) * 32, nw = (wid & 1) * 32;
    float c[2][4][4] = {};

    for (int k0 = 0; k0 < DD; k0 += 32) {
#pragma unroll
        for (int it = 0; it < 2; it++) {
            int flat = it * 128 + tid;
            int r = flat >> 2, c4 = flat & 3;
            size_t off = (size_t)(r0 + r) * DD + k0 + c4 * 8;
            uint4 a = *(const uint4*)(g_aoh + off);
            Ah[c4*4+0][r] = a.x; Ah[c4*4+1][r] = a.y; Ah[c4*4+2][r] = a.z; Ah[c4*4+3][r] = a.w;
            uint4 b = *(const uint4*)(g_aol + off);
            Al[c4*4+0][r] = b.x; Al[c4*4+1][r] = b.y; Al[c4*4+2][r] = b.z; Al[c4*4+3][r] = b.w;
        }
#pragma unroll
        for (int it = 0; it < 4; it++) {
            int flat = it * 128 + tid;
            int o = flat >> 3, c4 = flat & 7;
            float4 wv = *(const float4*)&wp[(size_t)(c0 + o) * DD + k0 + c4 * 4];
            unsigned h0, l0, h1, l1;
            split_pair(wv.x, wv.y, h0, l0);
            split_pair(wv.z, wv.w, h1, l1);
            Bh[c4*2][o] = h0; Bh[c4*2+1][o] = h1;
            Bl[c4*2][o] = l0; Bl[c4*2+1][o] = l1;
        }
        __syncthreads();
#pragma unroll
        for (int s = 0; s < 2; s++) compute_k16(Ah, Al, Bh, Bl, s*8, mw, nw, g, tg, c);
        __syncthreads();
    }

#pragma unroll
    for (int mi = 0; mi < 2; mi++)
#pragma unroll
        for (int ni = 0; ni < 4; ni++) {
            int row = r0 + mw + mi*16 + g;
            int col = c0 + nw + ni*8 + 2*tg;
#pragma unroll
            for (int rr = 0; rr < 2; rr++) {
                size_t off = (size_t)(row + rr*8) * DD + col;
                float2 xr = *(const float2*)&x[off];
                float2 r;
                r.x = c[mi][ni][rr*2+0] + xr.x;
                r.y = c[mi][ni][rr*2+1] + xr.y;
                *(float2*)&out[off] = r;
            }
        }
}

// ---------------------------------------------------------------- launch
extern "C" void kernel_launch(void* const* d_in, const int* in_sizes, int n_in,
                              void* d_out, int out_size) {
    const float* x     = (const float*)d_in[0];
    const float* Bb    = (const float*)d_in[1];
    const int*   M     = (const int*)  d_in[2];
    const float* gamma = (const float*)d_in[3];
    const float* beta  = (const float*)d_in[4];
    const float* wq    = (const float*)d_in[5];
    const float* wk    = (const float*)d_in[6];
    const float* wv    = (const float*)d_in[7];
    const float* wp    = (const float*)d_in[8];
    float* out = (float*)d_out;

    ln_kernel<<<NROWS, 128>>>(x, gamma, beta);
    qkv_kernel<<<dim3(NROWS / 64, NA, 3), 128>>>(wq, wk, wv);
    attn_kernel<<<dim3(THW / 64, NA * BSZ), 128>>>(Bb, M);
    proj_kernel<<<dim3(DD / 64, NROWS / 64), 128>>>(x, wp, out);
}

// round 7
// speedup vs baseline: 3.1450x; 1.6373x over previous
#include <cuda_runtime.h>
#include <cuda_bf16.h>

#define NA   8
#define BSZ  4
#define THW  1024
#define DD   512
#define DA   64
#define NROWS (BSZ*THW)   // 4096
#define NQKV (3*NA*DA)    // 1536

// ---------------- device scratch (allocation forbidden) ----------------
__device__ __nv_bfloat16 g_xh[NROWS*DD], g_xl[NROWS*DD];          // normalized x hi/lo
__device__ __nv_bfloat16 g_qh[NA*NROWS*DA], g_ql[NA*NROWS*DA];    // q (pre-scaled 1/8)
__device__ __nv_bfloat16 g_kh[NA*NROWS*DA], g_kl[NA*NROWS*DA];
__device__ __nv_bfloat16 g_vh[NA*NROWS*DA], g_vl[NA*NROWS*DA];
__device__ __nv_bfloat16 g_aoh[NROWS*DD], g_aol[NROWS*DD];        // concat attn out hi/lo
__device__ __nv_bfloat16 g_wth[NQKV*DD], g_wtl[NQKV*DD];          // qkv weights, [n][d]
__device__ __nv_bfloat16 g_wph[DD*DD],  g_wpl[DD*DD];             // proj weights, [o][i]

// ---------------- helpers ----------------
__device__ __forceinline__ void mma4(float c[4], const unsigned a[4], unsigned b0, unsigned b1) {
    asm volatile(
        "mma.sync.aligned.m16n8k16.row.col.f32.bf16.bf16.f32 "
        "{%0,%1,%2,%3}, {%4,%5,%6,%7}, {%8,%9}, {%0,%1,%2,%3};\n"
        : "+f"(c[0]), "+f"(c[1]), "+f"(c[2]), "+f"(c[3])
        : "r"(a[0]), "r"(a[1]), "r"(a[2]), "r"(a[3]), "r"(b0), "r"(b1));
}

__device__ __forceinline__ void ldsm4(unsigned& r0, unsigned& r1, unsigned& r2, unsigned& r3,
                                      const void* p) {
    unsigned addr = (unsigned)__cvta_generic_to_shared(p);
    asm volatile("ldmatrix.sync.aligned.m8n8.x4.shared.b16 {%0,%1,%2,%3}, [%4];"
                 : "=r"(r0), "=r"(r1), "=r"(r2), "=r"(r3) : "r"(addr));
}

__device__ __forceinline__ void ldsm4t(unsigned& r0, unsigned& r1, unsigned& r2, unsigned& r3,
                                       const void* p) {
    unsigned addr = (unsigned)__cvta_generic_to_shared(p);
    asm volatile("ldmatrix.sync.aligned.m8n8.x4.trans.shared.b16 {%0,%1,%2,%3}, [%4];"
                 : "=r"(r0), "=r"(r1), "=r"(r2), "=r"(r3) : "r"(addr));
}

__device__ __forceinline__ void cpa16(void* dst, const void* src) {
    unsigned d = (unsigned)__cvta_generic_to_shared(dst);
    asm volatile("cp.async.cg.shared.global [%0], [%1], 16;" :: "r"(d), "l"(src));
}
__device__ __forceinline__ void cp_commit() {
    asm volatile("cp.async.commit_group;" ::: "memory");
}
template<int N> __device__ __forceinline__ void cp_wait() {
    asm volatile("cp.async.wait_group %0;" :: "n"(N) : "memory");
}

__device__ __forceinline__ void split1(float x, __nv_bfloat16& h, __nv_bfloat16& l) {
    h = __float2bfloat16_rn(x);
    l = __float2bfloat16_rn(x - __bfloat162float(h));
}

__device__ __forceinline__ void split_pair(float a, float b, unsigned& hi, unsigned& lo) {
    __nv_bfloat16 ah = __float2bfloat16_rn(a), bh = __float2bfloat16_rn(b);
    float ar = a - __bfloat162float(ah), br = b - __bfloat162float(bh);
    __nv_bfloat162 h2; h2.x = ah; h2.y = bh;
    __nv_bfloat162 l2; l2.x = __float2bfloat16_rn(ar); l2.y = __float2bfloat16_rn(br);
    hi = *reinterpret_cast<unsigned*>(&h2);
    lo = *reinterpret_cast<unsigned*>(&l2);
}

// ---------------------------------------------------------------- LayerNorm
__global__ void ln_kernel(const float* __restrict__ x,
                          const float* __restrict__ gamma,
                          const float* __restrict__ beta) {
    int row = blockIdx.x;
    int t   = threadIdx.x;              // 128 threads
    const float* xr = x + (size_t)row * DD;
    float v[4];
    float s = 0.f;
#pragma unroll
    for (int i = 0; i < 4; i++) { v[i] = xr[i * 128 + t]; s += v[i]; }

    __shared__ float rbuf[4];
    __shared__ float stat;
#pragma unroll
    for (int o = 16; o > 0; o >>= 1) s += __shfl_xor_sync(0xffffffffu, s, o);
    if ((t & 31) == 0) rbuf[t >> 5] = s;
    __syncthreads();
    if (t == 0) stat = rbuf[0] + rbuf[1] + rbuf[2] + rbuf[3];
    __syncthreads();
    float mean = stat * (1.f / DD);

    float ss = 0.f;
#pragma unroll
    for (int i = 0; i < 4; i++) { float d = v[i] - mean; ss += d * d; }
    __syncthreads();
#pragma unroll
    for (int o = 16; o > 0; o >>= 1) ss += __shfl_xor_sync(0xffffffffu, ss, o);
    if ((t & 31) == 0) rbuf[t >> 5] = ss;
    __syncthreads();
    if (t == 0) stat = rbuf[0] + rbuf[1] + rbuf[2] + rbuf[3];
    __syncthreads();
    float rstd = rsqrtf(stat * (1.f / DD) + 1e-5f);

#pragma unroll
    for (int i = 0; i < 4; i++) {
        int c = i * 128 + t;
        float y = (v[i] - mean) * rstd * gamma[c] + beta[c];
        __nv_bfloat16 h, l; split1(y, h, l);
        g_xh[(size_t)row * DD + c] = h;
        g_xl[(size_t)row * DD + c] = l;
    }
}

// ------------------------------------------------- weight prep
// Wt[n][d], n = which*512 + h*64 + e, bf16 hi/lo
__global__ void prep_w(const float* __restrict__ wq,
                       const float* __restrict__ wk,
                       const float* __restrict__ wv) {
    int which = blockIdx.x >> 3, h = blockIdx.x & 7;
    const float* w = ((which == 0) ? wq : (which == 1) ? wk : wv) + (size_t)h * DD * DA;
    int e0 = blockIdx.y * 8;
#pragma unroll
    for (int it = 0; it < 8; it++) {
        int idx = it * 256 + threadIdx.x;   // 0..2047
        int e = e0 + (idx >> 8);
        int d = (idx & 255) * 2;
        float v0 = w[(size_t)d * DA + e];
        float v1 = w[(size_t)(d + 1) * DA + e];
        unsigned hi, lo; split_pair(v0, v1, hi, lo);
        size_t n = which * 512 + h * 64 + e;
        *(unsigned*)(g_wth + n * DD + d) = hi;
        *(unsigned*)(g_wtl + n * DD + d) = lo;
    }
}

__global__ void prep_wp(const float* __restrict__ wp) {
    size_t p = (size_t)blockIdx.x * 256 + threadIdx.x;   // grid 512
    float2 v = ((const float2*)wp)[p];
    unsigned hi, lo; split_pair(v.x, v.y, hi, lo);
    ((unsigned*)g_wph)[p] = hi;
    ((unsigned*)g_wpl)[p] = lo;
}

// ---------------------------------------------------------------- big GEMM
// C[128m x 64n] per block, 8 warps (4m x 2n), warp 32x32, k-tile 64, smem 48KB.
// A rows: Ah/Al [m][512], B rows: Bh/Bl [n][512]  (both k-contiguous bf16 hi/lo)
struct GemmAcc { float c[2][4][4]; };

__device__ __forceinline__ void gemm_mainloop(
    const __nv_bfloat16* Asrc_h, const __nv_bfloat16* Asrc_l,
    const __nv_bfloat16* Bsrc_h, const __nv_bfloat16* Bsrc_l,
    char* Ah, char* Al, char* Bh, char* Bl,
    int tid, int mw, int nw, int grp, int li, GemmAcc& acc)
{
    for (int k0 = 0; k0 < DD; k0 += 64) {
#pragma unroll
        for (int it = 0; it < 4; it++) {
            int flat = it * 256 + tid;
            int r = flat >> 3, cc = flat & 7;
            size_t so = (size_t)r * DD + k0 + cc * 8;
            int off = r * 128 + ((cc ^ (r & 7)) << 4);
            cpa16(Ah + off, Asrc_h + so);
            cpa16(Al + off, Asrc_l + so);
        }
#pragma unroll
        for (int it = 0; it < 2; it++) {
            int flat = it * 256 + tid;
            int r = flat >> 3, cc = flat & 7;
            size_t so = (size_t)r * DD + k0 + cc * 8;
            int off = r * 128 + ((cc ^ (r & 7)) << 4);
            cpa16(Bh + off, Bsrc_h + so);
            cpa16(Bl + off, Bsrc_l + so);
        }
        cp_commit();
        cp_wait<0>();
        __syncthreads();

#pragma unroll
        for (int s4 = 0; s4 < 4; s4++) {
            unsigned afh[2][4], afl[2][4];
#pragma unroll
            for (int mi = 0; mi < 2; mi++) {
                int ar = mw + mi * 16 + ((grp & 1) << 3) + li;
                int sw = (((s4 * 2 + (grp >> 1)) ^ (ar & 7)) << 4);
                ldsm4(afh[mi][0], afh[mi][1], afh[mi][2], afh[mi][3], Ah + ar * 128 + sw);
                ldsm4(afl[mi][0], afl[mi][1], afl[mi][2], afl[mi][3], Al + ar * 128 + sw);
            }
            unsigned bfh[2][4], bfl[2][4];
#pragma unroll
            for (int jp = 0; jp < 2; jp++) {
                int br = nw + jp * 16 + ((grp >> 1) << 3) + li;
                int sw = (((s4 * 2 + (grp & 1)) ^ (br & 7)) << 4);
                ldsm4(bfh[jp][0], bfh[jp][1], bfh[jp][2], bfh[jp][3], Bh + br * 128 + sw);
                ldsm4(bfl[jp][0], bfl[jp][1], bfl[jp][2], bfl[jp][3], Bl + br * 128 + sw);
            }
#pragma unroll
            for (int mi = 0; mi < 2; mi++)
#pragma unroll
                for (int jp = 0; jp < 2; jp++) {
                    float* c0 = acc.c[mi][jp * 2];
                    float* c1 = acc.c[mi][jp * 2 + 1];
                    mma4(c0, afh[mi], bfh[jp][0], bfh[jp][1]);
                    mma4(c0, afl[mi], bfh[jp][0], bfh[jp][1]);
                    mma4(c0, afh[mi], bfl[jp][0], bfl[jp][1]);
                    mma4(c1, afh[mi], bfh[jp][2], bfh[jp][3]);
                    mma4(c1, afl[mi], bfh[jp][2], bfh[jp][3]);
                    mma4(c1, afh[mi], bfl[jp][2], bfl[jp][3]);
                }
        }
        __syncthreads();
    }
}

// qkv GEMM: grid (4096/128, 1536/64), 256 thr
__global__ __launch_bounds__(256, 2) void qkv_g() {
    __shared__ __align__(16) char sm[49152];
    char* Ah = sm, *Al = sm + 16384, *Bh = sm + 32768, *Bl = sm + 40960;
    int m0 = blockIdx.x * 128, n0 = blockIdx.y * 64;
    int which = n0 >> 9, h = (n0 >> 6) & 7;

    int tid = threadIdx.x, lane = tid & 31, wid = tid >> 5;
    int g = lane >> 2, tg = lane & 3, grp = lane >> 3, li = lane & 7;
    int mw = (wid >> 1) * 32, nw = (wid & 1) * 32;

    GemmAcc acc = {};
    gemm_mainloop(g_xh + (size_t)m0 * DD, g_xl + (size_t)m0 * DD,
                  g_wth + (size_t)n0 * DD, g_wtl + (size_t)n0 * DD,
                  Ah, Al, Bh, Bl, tid, mw, nw, grp, li, acc);

    float scale = (which == 0) ? 0.125f : 1.0f;
    __nv_bfloat16* oh = (which == 0) ? g_qh : ((which == 1) ? g_kh : g_vh);
    __nv_bfloat16* ol = (which == 0) ? g_ql : ((which == 1) ? g_kl : g_vl);
#pragma unroll
    for (int mi = 0; mi < 2; mi++)
#pragma unroll
        for (int nj = 0; nj < 4; nj++) {
            int m = m0 + mw + mi * 16 + g;
            int e = nw + nj * 8 + 2 * tg;
            unsigned hi, lo;
            split_pair(acc.c[mi][nj][0] * scale, acc.c[mi][nj][1] * scale, hi, lo);
            *(unsigned*)(oh + ((size_t)(h * NROWS + m)) * DA + e) = hi;
            *(unsigned*)(ol + ((size_t)(h * NROWS + m)) * DA + e) = lo;
            split_pair(acc.c[mi][nj][2] * scale, acc.c[mi][nj][3] * scale, hi, lo);
            *(unsigned*)(oh + ((size_t)(h * NROWS + m + 8)) * DA + e) = hi;
            *(unsigned*)(ol + ((size_t)(h * NROWS + m + 8)) * DA + e) = lo;
        }
}

// proj GEMM + residual: grid (4096/128, 512/64), 256 thr
__global__ __launch_bounds__(256, 2) void proj_g(const float* __restrict__ x,
                                                 float* __restrict__ out) {
    __shared__ __align__(16) char sm[49152];
    char* Ah = sm, *Al = sm + 16384, *Bh = sm + 32768, *Bl = sm + 40960;
    int m0 = blockIdx.x * 128, n0 = blockIdx.y * 64;

    int tid = threadIdx.x, lane = tid & 31, wid = tid >> 5;
    int g = lane >> 2, tg = lane & 3, grp = lane >> 3, li = lane & 7;
    int mw = (wid >> 1) * 32, nw = (wid & 1) * 32;

    GemmAcc acc = {};
    gemm_mainloop(g_aoh + (size_t)m0 * DD, g_aol + (size_t)m0 * DD,
                  g_wph + (size_t)n0 * DD, g_wpl + (size_t)n0 * DD,
                  Ah, Al, Bh, Bl, tid, mw, nw, grp, li, acc);

#pragma unroll
    for (int mi = 0; mi < 2; mi++)
#pragma unroll
        for (int nj = 0; nj < 4; nj++) {
            int m = m0 + mw + mi * 16 + g;
            int n = n0 + nw + nj * 8 + 2 * tg;
#pragma unroll
            for (int rr = 0; rr < 2; rr++) {
                size_t off = (size_t)(m + rr * 8) * DD + n;
                float2 xr = *(const float2*)&x[off];
                float2 r;
                r.x = acc.c[mi][nj][rr * 2 + 0] + xr.x;
                r.y = acc.c[mi][nj][rr * 2 + 1] + xr.y;
                *(float2*)&out[off] = r;
            }
        }
}

// ---------------------------------------------------------------- fused attention
// grid (THW/128, NA*BSZ), 256 threads (8 warps, m16 each). k-tile = 32 tokens,
// double-buffered stages of 16KB (Kh 4K | Kl 4K | Vh 4K | Vl 4K).
__global__ __launch_bounds__(256) void attn_kernel(const float* __restrict__ Bb,
                                                   const int* __restrict__ M) {
    __shared__ __align__(16) char sm[2][16384];

    int hb = blockIdx.y;
    int h = hb >> 2, b = hb & 3;
    int qr0 = blockIdx.x * 128;

    int tid = threadIdx.x, lane = tid & 31, wid = tid >> 5;
    int g = lane >> 2, tg = lane & 3, grp = lane >> 3, li = lane & 7;
    int mw = wid * 16;

    size_t kv = (size_t)(h * NROWS + b * THW) * DA;

    // ---- Q tile into sm[0](hi)/sm[1](lo), extract frags ----
#pragma unroll
    for (int it = 0; it < 4; it++) {
        int flat = it * 256 + tid;
        int r = flat >> 3, cc = flat & 7;
        size_t so = kv + (size_t)(qr0 + r) * DA + cc * 8;
        int off = r * 128 + ((cc ^ (r & 7)) << 4);
        cpa16(sm[0] + off, g_qh + so);
        cpa16(sm[1] + off, g_ql + so);
    }
    cp_commit();
    cp_wait<0>();
    __syncthreads();

    unsigned qfh[4][4], qfl[4][4];
    {
        int qrow = mw + ((grp & 1) << 3) + li;
        int q7 = qrow & 7;
#pragma unroll
        for (int s4 = 0; s4 < 4; s4++) {
            int sw = (((s4 * 2 + (grp >> 1)) ^ q7) << 4);
            ldsm4(qfh[s4][0], qfh[s4][1], qfh[s4][2], qfh[s4][3], sm[0] + qrow * 128 + sw);
            ldsm4(qfl[s4][0], qfl[s4][1], qfl[s4][2], qfl[s4][3], sm[1] + qrow * 128 + sw);
        }
    }
    __syncthreads();

    // prefetch helper: stage kt -> sm[kt&1]; one cpa x4 per thread (32 rows x 8 chunks)
    {
        int r = tid >> 3, cc = tid & 7;
        size_t so = kv + (size_t)r * DA + cc * 8;
        int off = r * 128 + ((cc ^ (r & 7)) << 4);
        cpa16(sm[0] + off,         g_kh + so);
        cpa16(sm[0] + 4096 + off,  g_kl + so);
        cpa16(sm[0] + 8192 + off,  g_vh + so);
        cpa16(sm[0] + 12288 + off, g_vl + so);
        cp_commit();
    }

    float m0 = -1e30f, m1 = -1e30f, l0 = 0.f, l1 = 0.f;
    float O[8][4] = {};

    const float* Brow = Bb + ((size_t)hb * THW + (qr0 + mw + g)) * THW + 2 * tg;
    const int*   Mrow = M  + (size_t)(qr0 + mw + g) * THW + 2 * tg;

    int pr = tid >> 3, pc = tid & 7;
    int poff = pr * 128 + ((pc ^ (pr & 7)) << 4);

    for (int kt = 0; kt < 32; kt++) {
        if (kt < 31) {
            char* S = sm[(kt + 1) & 1];
            size_t so = kv + (size_t)((kt + 1) * 32 + pr) * DA + pc * 8;
            cpa16(S + poff,         g_kh + so);
            cpa16(S + 4096 + poff,  g_kl + so);
            cpa16(S + 8192 + poff,  g_vh + so);
            cpa16(S + 12288 + poff, g_vl + so);
            cp_commit();
            cp_wait<1>();
        } else {
            cp_wait<0>();
        }
        __syncthreads();
        char* S = sm[kt & 1];

        // ---- S = Q K^T (3-MMA split), 32 kcols -> sc[4][4] ----
        float sc[4][4] = {};
#pragma unroll
        for (int s4 = 0; s4 < 4; s4++) {
#pragma unroll
            for (int jp = 0; jp < 2; jp++) {
                int rr = jp * 16 + ((grp >> 1) << 3) + li;
                int sw = (((s4 * 2 + (grp & 1)) ^ (rr & 7)) << 4);
                unsigned h0, h1, h2, h3, e0, e1, e2, e3;
                ldsm4(h0, h1, h2, h3, S + rr * 128 + sw);
                ldsm4(e0, e1, e2, e3, S + 4096 + rr * 128 + sw);
                mma4(sc[2*jp],   qfh[s4], h0, h1);
                mma4(sc[2*jp],   qfl[s4], h0, h1);
                mma4(sc[2*jp],   qfh[s4], e0, e1);
                mma4(sc[2*jp+1], qfh[s4], h2, h3);
                mma4(sc[2*jp+1], qfl[s4], h2, h3);
                mma4(sc[2*jp+1], qfh[s4], e2, e3);
            }
        }

        // ---- bias + mask ----
        const float* Bp = Brow + kt * 32;
        const int*   Mp = Mrow + kt * 32;
#pragma unroll
        for (int j = 0; j < 4; j++) {
            float2 b0 = *(const float2*)(Bp + j * 8);
            int2   i0 = *(const int2*)  (Mp + j * 8);
            sc[j][0] = i0.x ? -10000.f : sc[j][0] + b0.x;
            sc[j][1] = i0.y ? -10000.f : sc[j][1] + b0.y;
            float2 b1 = *(const float2*)(Bp + 8 * THW + j * 8);
            int2   i1 = *(const int2*)  (Mp + 8 * THW + j * 8);
            sc[j][2] = i1.x ? -10000.f : sc[j][2] + b1.x;
            sc[j][3] = i1.y ? -10000.f : sc[j][3] + b1.y;
        }

        // ---- online softmax ----
        float rm0 = -1e30f, rm1 = -1e30f;
#pragma unroll
        for (int j = 0; j < 4; j++) {
            rm0 = fmaxf(rm0, fmaxf(sc[j][0], sc[j][1]));
            rm1 = fmaxf(rm1, fmaxf(sc[j][2], sc[j][3]));
        }
        rm0 = fmaxf(rm0, __shfl_xor_sync(0xffffffffu, rm0, 1));
        rm0 = fmaxf(rm0, __shfl_xor_sync(0xffffffffu, rm0, 2));
        rm1 = fmaxf(rm1, __shfl_xor_sync(0xffffffffu, rm1, 1));
        rm1 = fmaxf(rm1, __shfl_xor_sync(0xffffffffu, rm1, 2));
        float nm0 = fmaxf(m0, rm0), nm1 = fmaxf(m1, rm1);
        float a0 = __expf(m0 - nm0), a1 = __expf(m1 - nm1);
        float ls0 = 0.f, ls1 = 0.f;
#pragma unroll
        for (int j = 0; j < 4; j++) {
            sc[j][0] = __expf(sc[j][0] - nm0); ls0 += sc[j][0];
            sc[j][1] = __expf(sc[j][1] - nm0); ls0 += sc[j][1];
            sc[j][2] = __expf(sc[j][2] - nm1); ls1 += sc[j][2];
            sc[j][3] = __expf(sc[j][3] - nm1); ls1 += sc[j][3];
        }
        ls0 += __shfl_xor_sync(0xffffffffu, ls0, 1);
        ls0 += __shfl_xor_sync(0xffffffffu, ls0, 2);
        ls1 += __shfl_xor_sync(0xffffffffu, ls1, 1);
        ls1 += __shfl_xor_sync(0xffffffffu, ls1, 2);
        l0 = l0 * a0 + ls0;
        l1 = l1 * a1 + ls1;
        m0 = nm0; m1 = nm1;
#pragma unroll
        for (int j = 0; j < 8; j++) {
            O[j][0] *= a0; O[j][1] *= a0;
            O[j][2] *= a1; O[j][3] *= a1;
        }

        // ---- O += P V ----
#pragma unroll
        for (int t = 0; t < 2; t++) {
            unsigned ph[4], pl[4];
            split_pair(sc[2*t][0],   sc[2*t][1],   ph[0], pl[0]);
            split_pair(sc[2*t][2],   sc[2*t][3],   ph[1], pl[1]);
            split_pair(sc[2*t+1][0], sc[2*t+1][1], ph[2], pl[2]);
            split_pair(sc[2*t+1][2], sc[2*t+1][3], ph[3], pl[3]);
            int rr = 16 * t + ((grp & 1) << 3) + li;
            int r7 = rr & 7;
#pragma unroll
            for (int jp = 0; jp < 4; jp++) {
                int sw = (((2 * jp + (grp >> 1)) ^ r7) << 4);
                unsigned h0, h1, h2, h3, e0, e1, e2, e3;
                ldsm4t(h0, h1, h2, h3, S + 8192  + rr * 128 + sw);
                ldsm4t(e0, e1, e2, e3, S + 12288 + rr * 128 + sw);
                mma4(O[2*jp],   ph, h0, h1);
                mma4(O[2*jp],   pl, h0, h1);
                mma4(O[2*jp],   ph, e0, e1);
                mma4(O[2*jp+1], ph, h2, h3);
                mma4(O[2*jp+1], pl, h2, h3);
                mma4(O[2*jp+1], ph, e2, e3);
            }
        }
        __syncthreads();
    }

    // ---- normalize + write ----
    float inv0 = 1.f / l0, inv1 = 1.f / l1;
    int tok0 = b * THW + qr0 + mw + g;
#pragma unroll
    for (int j = 0; j < 8; j++) {
        int col = h * DA + j * 8 + 2 * tg;
        unsigned hi, lo;
        split_pair(O[j][0] * inv0, O[j][1] * inv0, hi, lo);
        *(unsigned*)(g_aoh + (size_t)tok0 * DD + col) = hi;
        *(unsigned*)(g_aol + (size_t)tok0 * DD + col) = lo;
        split_pair(O[j][2] * inv1, O[j][3] * inv1, hi, lo);
        *(unsigned*)(g_aoh + (size_t)(tok0 + 8) * DD + col) = hi;
        *(unsigned*)(g_aol + (size_t)(tok0 + 8) * DD + col) = lo;
    }
}

// ---------------------------------------------------------------- launch
extern "C" void kernel_launch(void* const* d_in, const int* in_sizes, int n_in,
                              void* d_out, int out_size) {
    const float* x     = (const float*)d_in[0];
    const float* Bb    = (const float*)d_in[1];
    const int*   M     = (const int*)  d_in[2];
    const float* gamma = (const float*)d_in[3];
    const float* beta  = (const float*)d_in[4];
    const float* wq    = (const float*)d_in[5];
    const float* wk    = (const float*)d_in[6];
    const float* wv    = (const float*)d_in[7];
    const float* wp    = (const float*)d_in[8];
    float* out = (float*)d_out;

    ln_kernel<<<NROWS, 128>>>(x, gamma, beta);
    prep_w<<<dim3(24, 8), 256>>>(wq, wk, wv);
    prep_wp<<<512, 256>>>(wp);
    qkv_g<<<dim3(NROWS / 128, NQKV / 64), 256>>>();
    attn_kernel<<<dim3(THW / 128, NA * BSZ), 256>>>(Bb, M);
    proj_g<<<dim3(NROWS / 128, DD / 64), 256>>>(x, out);
}